// round 1
// baseline (speedup 1.0000x reference)
#include <cuda_runtime.h>
#include <cuda_bf16.h>
#include <cstdint>

// Problem shape (fixed by setup_inputs): B=4, H=512, W=256
// 2048 independent (b,h) attention problems over a 2-channel feature.
//
// Layout assumptions:
//   d_in[0] = x1 [B,H,W] f32, d_in[1] = x2 [B,H,W] f32
//   d_in[2] = wq [2,2] row-major (o,i), d_in[3] = bq [2]
//   d_in[4] = wk, d_in[5] = bk, d_in[6] = wv, d_in[7] = bv
//   d_out   = out1 (B*H*W floats) followed by out2 (B*H*W floats)

#define W_DIM 256
#define BH_TOTAL (4 * 512)
#define PLANE (4 * 512 * 256)

__global__ __launch_bounds__(W_DIM) void channel_attn_kernel(
    const float* __restrict__ x1, const float* __restrict__ x2,
    const float* __restrict__ wq, const float* __restrict__ bq,
    const float* __restrict__ wk, const float* __restrict__ bk,
    const float* __restrict__ wv, const float* __restrict__ bv,
    float* __restrict__ out)
{
    const int bh   = blockIdx.x;
    const int tid  = threadIdx.x;
    const int base = bh * W_DIM;

    // k0,k1,v0,v1 packed per key position -> one broadcast LDS.128 per iter
    __shared__ float4 kv[W_DIM];

    const float a = x1[base + tid];
    const float b = x2[base + tid];

    // 1x1 conv projections (2x2 channel matmul), weights row-major [o][i]
    const float q0 = fmaf(wq[0], a, fmaf(wq[1], b, bq[0]));
    const float q1 = fmaf(wq[2], a, fmaf(wq[3], b, bq[1]));
    const float k0 = fmaf(wk[0], a, fmaf(wk[1], b, bk[0]));
    const float k1 = fmaf(wk[2], a, fmaf(wk[3], b, bk[1]));
    const float v0 = fmaf(wv[0], a, fmaf(wv[1], b, bv[0]));
    const float v1 = fmaf(wv[2], a, fmaf(wv[3], b, bv[1]));

    kv[tid] = make_float4(k0, k1, v0, v1);
    __syncthreads();

    // ---- pass 1: exact row max of s(u) = q0*k0[u] + q1*k1[u] ----
    float m = -__int_as_float(0x7f800000);  // -inf
#pragma unroll 8
    for (int u = 0; u < W_DIM; ++u) {
        const float4 t = kv[u];
        const float s = fmaf(q0, t.x, q1 * t.y);
        m = fmaxf(m, s);
    }

    // ---- pass 2: exp + weighted accumulation (base-2, pre-scaled) ----
    const float L2E = 1.4426950408889634f;
    const float q0e = q0 * L2E;
    const float q1e = q1 * L2E;
    const float mb  = m * L2E;

    float sum = 0.0f, a0 = 0.0f, a1 = 0.0f;
#pragma unroll 8
    for (int u = 0; u < W_DIM; ++u) {
        const float4 t = kv[u];
        const float p = fmaf(q0e, t.x, fmaf(q1e, t.y, -mb));  // <= ~0
        float e;
        asm("ex2.approx.ftz.f32 %0, %1;" : "=f"(e) : "f"(p));
        sum += e;
        a0 = fmaf(e, t.z, a0);
        a1 = fmaf(e, t.w, a1);
    }

    float inv;
    asm("rcp.approx.ftz.f32 %0, %1;" : "=f"(inv) : "f"(sum));

    // residual add fused into the store
    out[base + tid]         = fmaf(a0, inv, a);
    out[PLANE + base + tid] = fmaf(a1, inv, b);
}

extern "C" void kernel_launch(void* const* d_in, const int* in_sizes, int n_in,
                              void* d_out, int out_size)
{
    (void)in_sizes; (void)n_in; (void)out_size;
    channel_attn_kernel<<<BH_TOTAL, W_DIM>>>(
        (const float*)d_in[0], (const float*)d_in[1],
        (const float*)d_in[2], (const float*)d_in[3],
        (const float*)d_in[4], (const float*)d_in[5],
        (const float*)d_in[6], (const float*)d_in[7],
        (float*)d_out);
}

// round 2
// speedup vs baseline: 1.6529x; 1.6529x over previous
#include <cuda_runtime.h>
#include <cuda_bf16.h>
#include <cstdint>

// ChannelSelfAttention: B=4,H=512,W=256. 2048 independent W x W attentions
// over a 2-channel feature. One CTA per (b,h); thread = one query position.
//
// Single-pass softmax with a safe upper bound m_hat >= max score (softmax is
// shift-invariant; m_hat only needs to prevent overflow, p <= 0 guaranteed).
// All inner-loop math packed as f32x2 (FFMA2), 2 key positions per iteration.

#define W_DIM 256
#define BH_TOTAL 2048
#define PLANE (2048 * 256)

__device__ __forceinline__ uint32_t smem_u32(const void* p) {
    uint32_t a;
    asm("{ .reg .u64 t; cvta.to.shared.u64 t, %1; cvt.u32.u64 %0, t; }"
        : "=r"(a) : "l"(p));
    return a;
}
__device__ __forceinline__ uint64_t pk2(float lo, float hi) {
    uint64_t r; asm("mov.b64 %0, {%1, %2};" : "=l"(r) : "f"(lo), "f"(hi)); return r;
}
__device__ __forceinline__ void upk2(float& lo, float& hi, uint64_t v) {
    asm("mov.b64 {%0, %1}, %2;" : "=f"(lo), "=f"(hi) : "l"(v));
}
__device__ __forceinline__ uint64_t fma2(uint64_t a, uint64_t b, uint64_t c) {
    uint64_t d; asm("fma.rn.f32x2 %0, %1, %2, %3;" : "=l"(d) : "l"(a), "l"(b), "l"(c)); return d;
}
__device__ __forceinline__ uint64_t add2(uint64_t a, uint64_t b) {
    uint64_t d; asm("add.rn.f32x2 %0, %1, %2;" : "=l"(d) : "l"(a), "l"(b)); return d;
}
__device__ __forceinline__ float ex2f(float x) {
    float r; asm("ex2.approx.ftz.f32 %0, %1;" : "=f"(r) : "f"(x)); return r;
}

__global__ __launch_bounds__(W_DIM) void channel_attn_kernel(
    const float* __restrict__ x1, const float* __restrict__ x2,
    const float* __restrict__ wq, const float* __restrict__ bq,
    const float* __restrict__ wk, const float* __restrict__ bk,
    const float* __restrict__ wv, const float* __restrict__ bv,
    float* __restrict__ out)
{
    const int bh   = blockIdx.x;
    const int tid  = threadIdx.x;
    const int base = bh * W_DIM;

    // Pairwise SoA: entry j holds (k0[2j], k0[2j+1], k1[2j], k1[2j+1])
    __shared__ __align__(16) float kArr[2 * W_DIM];
    __shared__ __align__(16) float vArr[2 * W_DIM];
    __shared__ float red[16];

    const float a = x1[base + tid];
    const float b = x2[base + tid];

    const float q0 = fmaf(wq[0], a, fmaf(wq[1], b, bq[0]));
    const float q1 = fmaf(wq[2], a, fmaf(wq[3], b, bq[1]));
    const float k0 = fmaf(wk[0], a, fmaf(wk[1], b, bk[0]));
    const float k1 = fmaf(wk[2], a, fmaf(wk[3], b, bk[1]));
    const float v0 = fmaf(wv[0], a, fmaf(wv[1], b, bv[0]));
    const float v1 = fmaf(wv[2], a, fmaf(wv[3], b, bv[1]));

    {
        const int j = tid >> 1, h = tid & 1;
        kArr[4 * j + h]     = k0;
        kArr[4 * j + 2 + h] = k1;
        vArr[4 * j + h]     = v0;
        vArr[4 * j + 2 + h] = v1;
    }

    // One-time per-CTA reduction: max|k0|, max|k1|
    float ak0 = fabsf(k0), ak1 = fabsf(k1);
#pragma unroll
    for (int o = 16; o; o >>= 1) {
        ak0 = fmaxf(ak0, __shfl_xor_sync(0xffffffffu, ak0, o));
        ak1 = fmaxf(ak1, __shfl_xor_sync(0xffffffffu, ak1, o));
    }
    const int wid = tid >> 5;
    if ((tid & 31) == 0) { red[wid] = ak0; red[8 + wid] = ak1; }
    __syncthreads();

    float mk0 = red[0], mk1 = red[8];
#pragma unroll
    for (int w = 1; w < 8; ++w) {
        mk0 = fmaxf(mk0, red[w]);
        mk1 = fmaxf(mk1, red[8 + w]);
    }

    const float L2E = 1.4426950408889634f;
    const float q0e = q0 * L2E;
    const float q1e = q1 * L2E;
    // m_hat >= |q0e*k0[u] + q1e*k1[u]| for all u  =>  p = s - m_hat <= 0
    const float mhat = fmaf(fabsf(q0e), mk0, fabsf(q1e) * mk1);

    const uint64_t q02 = pk2(q0e, q0e);
    const uint64_t q12 = pk2(q1e, q1e);
    const uint64_t mn2 = pk2(-mhat, -mhat);

    uint64_t sum2 = 0ull, a02 = 0ull, a12 = 0ull;  // (0.0f, 0.0f) bit patterns
    const uint32_t kb = smem_u32(kArr);
    const uint32_t vb = smem_u32(vArr);

#pragma unroll 4
    for (int u = 0; u < W_DIM / 2; ++u) {
        uint64_t kk01, kk23, vv01, vv23;
        asm("ld.shared.v2.u64 {%0, %1}, [%2];"
            : "=l"(kk01), "=l"(kk23) : "r"(kb + 16u * u));
        asm("ld.shared.v2.u64 {%0, %1}, [%2];"
            : "=l"(vv01), "=l"(vv23) : "r"(vb + 16u * u));

        const uint64_t p2 = fma2(q02, kk01, fma2(q12, kk23, mn2));
        float pl, ph;
        upk2(pl, ph, p2);
        const uint64_t e2 = pk2(ex2f(pl), ex2f(ph));

        sum2 = add2(sum2, e2);
        a02  = fma2(e2, vv01, a02);
        a12  = fma2(e2, vv23, a12);
    }

    float sl, sh, a0l, a0h, a1l, a1h;
    upk2(sl, sh, sum2);
    upk2(a0l, a0h, a02);
    upk2(a1l, a1h, a12);

    float inv;
    asm("rcp.approx.ftz.f32 %0, %1;" : "=f"(inv) : "f"(sl + sh));

    out[base + tid]         = fmaf(a0l + a0h, inv, a);
    out[PLANE + base + tid] = fmaf(a1l + a1h, inv, b);
}

extern "C" void kernel_launch(void* const* d_in, const int* in_sizes, int n_in,
                              void* d_out, int out_size)
{
    (void)in_sizes; (void)n_in; (void)out_size;
    channel_attn_kernel<<<BH_TOTAL, W_DIM>>>(
        (const float*)d_in[0], (const float*)d_in[1],
        (const float*)d_in[2], (const float*)d_in[3],
        (const float*)d_in[4], (const float*)d_in[5],
        (const float*)d_in[6], (const float*)d_in[7],
        (float*)d_out);
}